// round 1
// baseline (speedup 1.0000x reference)
#include <cuda_runtime.h>
#include <math.h>

// Problem constants
#define BB 4
#define SS 1024
#define DD 1024
#define NQ 8
#define BSROWS (BB*SS)           // 4096
#define CLS_SCALE (0.7f/128.0f)  // ALPHA / (H * sqrt(HEAD_DIM))

// ---------------- scratch (device globals: allocation-free rule) ----------------
__device__ float g_Q[BSROWS*DD];
__device__ float g_K[BSROWS*DD];
__device__ float g_V[BSROWS*DD];
__device__ float g_SC[BB*SS*SS];     // scaled classical scores
__device__ float g_ATTN[BB*SS*SS];   // attention probabilities
__device__ float g_AT[BSROWS*DD];    // attended = attn @ V
__device__ float g_Sa[BSROWS], g_Ta[BSROWS], g_Sb[BSROWS], g_Tb[BSROWS];

// ---------------- SGEMM: C = scale * A @ op(B) (+ bias) ----------------
// A: [M,K] row-major. TRANSB: B is [N,K] row-major (C=A@B^T). else B is [K,N].
// Batched via blockIdx.z with element strides.
template<bool TRANSB>
__global__ __launch_bounds__(256)
void sgemm_kernel(const float* __restrict__ A, const float* __restrict__ B,
                  const float* __restrict__ bias, float* __restrict__ C,
                  int M, int N, int K, float scale,
                  long strideA, long strideB, long strideC)
{
    constexpr int BM = 128, BN = 128, BK = 16, TM = 8, TN = 8;
    __shared__ float As[BK][BM + 4];
    __shared__ float Bs[BK][BN + 4];

    const long b = blockIdx.z;
    A += b * strideA; B += b * strideB; C += b * strideC;

    const int tid  = threadIdx.x;
    const int row0 = blockIdx.y * BM;
    const int col0 = blockIdx.x * BN;

    const int tx = tid & 15;   // 0..15 -> 8 cols each
    const int ty = tid >> 4;   // 0..15 -> 8 rows each

    // A/B(NT) loads: float4 along K
    const int aRow = tid >> 2;        // 0..63
    const int aCol = (tid & 3) * 4;   // 0,4,8,12
    // B(NN) loads: float4 along N
    const int bRow = tid >> 5;        // 0..7
    const int bCol = (tid & 31) * 4;  // 0..124

    float acc[TM][TN];
    #pragma unroll
    for (int i = 0; i < TM; i++)
        #pragma unroll
        for (int j = 0; j < TN; j++) acc[i][j] = 0.f;

    for (int k0 = 0; k0 < K; k0 += BK) {
        #pragma unroll
        for (int i = 0; i < 2; i++) {
            int r = aRow + i * 64;
            float4 v = *(const float4*)&A[(long)(row0 + r) * K + k0 + aCol];
            As[aCol + 0][r] = v.x; As[aCol + 1][r] = v.y;
            As[aCol + 2][r] = v.z; As[aCol + 3][r] = v.w;
        }
        if (TRANSB) {
            #pragma unroll
            for (int i = 0; i < 2; i++) {
                int n = aRow + i * 64;
                float4 v = *(const float4*)&B[(long)(col0 + n) * K + k0 + aCol];
                Bs[aCol + 0][n] = v.x; Bs[aCol + 1][n] = v.y;
                Bs[aCol + 2][n] = v.z; Bs[aCol + 3][n] = v.w;
            }
        } else {
            #pragma unroll
            for (int i = 0; i < 2; i++) {
                int kk = bRow + i * 8;
                float4 v = *(const float4*)&B[(long)(k0 + kk) * N + col0 + bCol];
                *(float4*)&Bs[kk][bCol] = v;
            }
        }
        __syncthreads();

        #pragma unroll
        for (int kk = 0; kk < BK; kk++) {
            float a[TM], bb[TN];
            #pragma unroll
            for (int i = 0; i < TM; i += 4) {
                float4 v = *(const float4*)&As[kk][ty * TM + i];
                a[i] = v.x; a[i+1] = v.y; a[i+2] = v.z; a[i+3] = v.w;
            }
            #pragma unroll
            for (int j = 0; j < TN; j += 4) {
                float4 v = *(const float4*)&Bs[kk][tx * TN + j];
                bb[j] = v.x; bb[j+1] = v.y; bb[j+2] = v.z; bb[j+3] = v.w;
            }
            #pragma unroll
            for (int i = 0; i < TM; i++)
                #pragma unroll
                for (int j = 0; j < TN; j++)
                    acc[i][j] += a[i] * bb[j];
        }
        __syncthreads();
    }

    #pragma unroll
    for (int i = 0; i < TM; i++) {
        int r = row0 + ty * TM + i;
        #pragma unroll
        for (int j = 0; j < TN; j += 4) {
            int c = col0 + tx * TN + j;
            float4 v;
            v.x = acc[i][j+0] * scale;
            v.y = acc[i][j+1] * scale;
            v.z = acc[i][j+2] * scale;
            v.w = acc[i][j+3] * scale;
            if (bias) {
                v.x += bias[c+0]; v.y += bias[c+1];
                v.z += bias[c+2]; v.w += bias[c+3];
            }
            *(float4*)&C[(long)r * N + c] = v;
        }
    }
}

// ---------------- per-row quantum scalars ----------------
// a_m = exp(tanh(x_m)), S = sum a_m, T = sum a_m * tanh(x_m)  (m < NQ)
__global__ void row_stats_kernel(const float* __restrict__ query,
                                 const float* __restrict__ key)
{
    int r = blockIdx.x * blockDim.x + threadIdx.x;
    if (r >= 2 * BSROWS) return;
    const float* x = (r < BSROWS) ? &query[(long)r * DD]
                                  : &key[(long)(r - BSROWS) * DD];
    float s = 0.f, t = 0.f;
    #pragma unroll
    for (int m = 0; m < NQ; m++) {
        float v = tanhf(x[m]);
        float a = expf(v);
        s += a; t += a * v;
    }
    if (r < BSROWS) { g_Sa[r] = s; g_Ta[r] = t; }
    else            { g_Sb[r - BSROWS] = s; g_Tb[r - BSROWS] = t; }
}

// ---------------- fused quantum + softmax ----------------
// combined[j] = sc[j] + 0.3 * ( log(Sa_i+Sb_j) - (Ta_i+Tb_j)/(Sa_i+Sb_j) )
// attn written to g_ATTN and (optionally) directly to d_out's attn region.
__global__ __launch_bounds__(256)
void softmax_quantum_kernel(float* __restrict__ attn_out)
{
    const int row = blockIdx.x;       // b*S + i
    const int b   = row >> 10;
    const int tid = threadIdx.x;
    const float* sc = &g_SC[(long)row * SS];
    float* out      = &g_ATTN[(long)row * SS];
    const float Sa = g_Sa[row], Ta = g_Ta[row];

    __shared__ float sred[8];
    float v[4];
    float mx = -1e30f;

    #pragma unroll
    for (int u = 0; u < 4; u++) {
        int j = u * 256 + tid;
        float Sb = g_Sb[b * SS + j];
        float Tb = g_Tb[b * SS + j];
        float Z  = Sa + Sb;
        float q  = logf(Z) - (Ta + Tb) / Z;
        float c  = sc[j] + 0.3f * q;
        v[u] = c;
        mx = fmaxf(mx, c);
    }
    // block max
    #pragma unroll
    for (int o = 16; o > 0; o >>= 1) mx = fmaxf(mx, __shfl_xor_sync(0xffffffffu, mx, o));
    if ((tid & 31) == 0) sred[tid >> 5] = mx;
    __syncthreads();
    if (tid == 0) {
        float x = sred[0];
        #pragma unroll
        for (int w = 1; w < 8; w++) x = fmaxf(x, sred[w]);
        sred[0] = x;
    }
    __syncthreads();
    mx = sred[0];
    __syncthreads();

    float sum = 0.f;
    #pragma unroll
    for (int u = 0; u < 4; u++) {
        v[u] = expf(v[u] - mx);
        sum += v[u];
    }
    #pragma unroll
    for (int o = 16; o > 0; o >>= 1) sum += __shfl_xor_sync(0xffffffffu, sum, o);
    if ((tid & 31) == 0) sred[tid >> 5] = sum;
    __syncthreads();
    if (tid == 0) {
        float x = 0.f;
        #pragma unroll
        for (int w = 0; w < 8; w++) x += sred[w];
        sred[0] = x;
    }
    __syncthreads();
    const float inv = 1.0f / sred[0];

    #pragma unroll
    for (int u = 0; u < 4; u++) {
        int j = u * 256 + tid;
        float p = v[u] * inv;
        out[j] = p;
        if (attn_out) attn_out[(long)row * SS + j] = p;
    }
}

// ---------------- launcher ----------------
extern "C" void kernel_launch(void* const* d_in, const int* in_sizes, int n_in,
                              void* d_out, int out_size)
{
    const float* query = (const float*)d_in[0];
    const float* key   = (const float*)d_in[1];
    const float* value = (const float*)d_in[2];
    const float* Wq    = (const float*)d_in[3];
    const float* bq    = (const float*)d_in[4];
    const float* Wk    = (const float*)d_in[5];
    const float* bk    = (const float*)d_in[6];
    const float* Wv    = (const float*)d_in[7];
    const float* bv    = (const float*)d_in[8];
    const float* Wo    = (const float*)d_in[9];
    const float* bo    = (const float*)d_in[10];
    float* out = (float*)d_out;

    float *Qp, *Kp, *Vp, *SCp, *ATTNp, *ATp;
    cudaGetSymbolAddress((void**)&Qp,    g_Q);
    cudaGetSymbolAddress((void**)&Kp,    g_K);
    cudaGetSymbolAddress((void**)&Vp,    g_V);
    cudaGetSymbolAddress((void**)&SCp,   g_SC);
    cudaGetSymbolAddress((void**)&ATTNp, g_ATTN);
    cudaGetSymbolAddress((void**)&ATp,   g_AT);

    const long OUT_N  = (long)BB * SS * DD;   // 4194304
    const long ATTN_N = (long)BB * SS * SS;   // 4194304
    float* attn_out = ((long)out_size >= OUT_N + ATTN_N) ? (out + OUT_N) : nullptr;

    dim3 blk(256);
    dim3 gProj(DD / 128, BSROWS / 128);        // (8, 32)
    dim3 gBat(SS / 128, SS / 128, BB);         // (8, 8, 4)

    // 1) projections: X @ W^T + b
    sgemm_kernel<true><<<gProj, blk>>>(query, Wq, bq, Qp, BSROWS, DD, DD, 1.0f, 0, 0, 0);
    sgemm_kernel<true><<<gProj, blk>>>(key,   Wk, bk, Kp, BSROWS, DD, DD, 1.0f, 0, 0, 0);
    sgemm_kernel<true><<<gProj, blk>>>(value, Wv, bv, Vp, BSROWS, DD, DD, 1.0f, 0, 0, 0);

    // 2) per-row quantum scalars
    row_stats_kernel<<<(2 * BSROWS + 255) / 256, 256>>>(query, key);

    // 3) classical scores: SC[b] = (alpha/(H*sqrt(hd))) * Q[b] @ K[b]^T
    sgemm_kernel<true><<<gBat, blk>>>(Qp, Kp, nullptr, SCp, SS, SS, DD, CLS_SCALE,
                                      (long)SS * DD, (long)SS * DD, (long)SS * SS);

    // 4) fused quantum term + row softmax -> attn
    softmax_quantum_kernel<<<BSROWS, 256>>>(attn_out);

    // 5) attended[b] = attn[b] @ V[b]
    sgemm_kernel<false><<<gBat, blk>>>(ATTNp, Vp, nullptr, ATp, SS, SS, SS, 1.0f,
                                       (long)SS * SS, (long)SS * DD, (long)SS * DD);

    // 6) output = attended @ Wo^T + bo
    sgemm_kernel<true><<<gProj, blk>>>(ATp, Wo, bo, out, BSROWS, DD, DD, 1.0f, 0, 0, 0);
}

// round 3
// speedup vs baseline: 2.6580x; 2.6580x over previous
#include <cuda_runtime.h>
#include <cuda_bf16.h>
#include <math.h>
#include <stdint.h>

// ---------------- problem constants ----------------
#define BB 4
#define SS 1024
#define DD 1024
#define NQ 8
#define BSROWS (BB*SS)           // 4096
#define CLS_SCALE (0.7f/128.0f)  // ALPHA / (H*sqrt(HEAD_DIM))

#define NM (BSROWS*DD)           // 4,194,304
#define NW (DD*DD)               // 1,048,576

// ---------------- scratch (device globals; 16B-aligned via uint4) ----------------
__device__ uint4 g_qhi[NM/8], g_qlo[NM/8];
__device__ uint4 g_khi[NM/8], g_klo[NM/8];
__device__ uint4 g_vhi[NM/8], g_vlo[NM/8];
__device__ uint4 g_wqhi[NW/8], g_wqlo[NW/8];
__device__ uint4 g_wkhi[NW/8], g_wklo[NW/8];
__device__ uint4 g_wvhi[NW/8], g_wvlo[NW/8];
__device__ uint4 g_wohi[NW/8], g_wolo[NW/8];
__device__ uint4 g_Qhi[NM/8],  g_Qlo[NM/8];
__device__ uint4 g_Khi[NM/8],  g_Klo[NM/8];
__device__ uint4 g_VThi[NM/8], g_VTlo[NM/8];
__device__ uint4 g_Phi[NM/8],  g_Plo[NM/8];
__device__ uint4 g_AThi[NM/8], g_ATlo[NM/8];
__device__ float g_V[NM];
__device__ float g_SC[NM];
__device__ float g_Sa[BSROWS], g_Ta[BSROWS], g_Sb[BSROWS], g_Tb[BSROWS];

// ---------------- PTX helpers (non-'a' features only: sm_80-class) ----------------
__device__ __forceinline__ uint32_t smem_u32(const void* p) {
    uint32_t a;
    asm("{ .reg .u64 t; cvta.to.shared.u64 t, %1; cvt.u32.u64 %0, t; }" : "=r"(a) : "l"(p));
    return a;
}
__device__ __forceinline__ void cp16(uint32_t dst, const void* src) {
    asm volatile("cp.async.cg.shared.global [%0], [%1], 16;" :: "r"(dst), "l"(src) : "memory");
}
__device__ __forceinline__ void cp_commit() { asm volatile("cp.async.commit_group;" ::: "memory"); }
__device__ __forceinline__ void cp_wait0()  { asm volatile("cp.async.wait_group 0;"  ::: "memory"); }
__device__ __forceinline__ void cp_wait1()  { asm volatile("cp.async.wait_group 1;"  ::: "memory"); }

__device__ __forceinline__ void ldsm4(uint32_t& r0, uint32_t& r1, uint32_t& r2, uint32_t& r3,
                                      uint32_t addr) {
    asm volatile("ldmatrix.sync.aligned.m8n8.x4.shared.b16 {%0,%1,%2,%3}, [%4];"
                 : "=r"(r0), "=r"(r1), "=r"(r2), "=r"(r3) : "r"(addr));
}
__device__ __forceinline__ void mma16816(float* c, const uint32_t* a, const uint32_t* b) {
    asm volatile("mma.sync.aligned.m16n8k16.row.col.f32.bf16.bf16.f32 "
                 "{%0,%1,%2,%3}, {%4,%5,%6,%7}, {%8,%9}, {%0,%1,%2,%3};"
                 : "+f"(c[0]), "+f"(c[1]), "+f"(c[2]), "+f"(c[3])
                 : "r"(a[0]), "r"(a[1]), "r"(a[2]), "r"(a[3]), "r"(b[0]), "r"(b[1]));
}

// ---------------- HMMA GEMM: C = scale*(Ahi+Alo)@(Bhi+Blo)^T (+bias) ----------------
// A: [M,K] row-major bf16 hi/lo. B: [N,K] row-major bf16 hi/lo (NT form).
// Tile: BM=128 x BN=128 x BK=64. 8 warps (2x4), warp tile 64x32. Double-buffered cp.async.
#define BM 128
#define BN 128
#define BKK 64
#define NT_THREADS 256
// stage layout: [Ahi 16K][Alo 16K][Bhi 16K][Blo 16K] = 64KB; rows are 128B, XOR-8 swizzled
#define OFF_ALO 16384
#define OFF_BHI 32768
#define OFF_BLO 49152
#define STAGE_BYTES 65536
#define SMEM_GEMM (2*STAGE_BYTES)

__device__ __forceinline__ void load_stage(
    uint32_t st, const __nv_bfloat16* a_hi, const __nv_bfloat16* a_lo,
    const __nv_bfloat16* b_hi, const __nv_bfloat16* b_lo, int K, int k0, int tid)
{
    // A: 128 rows x 8 chunks(16B) = 1024 chunks -> 4 per thread; same for B.
    #pragma unroll
    for (int i = 0; i < 4; i++) {
        int id = tid + i * 256;
        int r = id >> 3, c = id & 7;
        uint32_t off = (uint32_t)(r * 128 + ((c ^ (r & 7)) << 4));
        size_t ge = (size_t)r * K + k0 + c * 8;
        cp16(st + off,           a_hi + ge);
        cp16(st + OFF_ALO + off, a_lo + ge);
        cp16(st + OFF_BHI + off, b_hi + ge);
        cp16(st + OFF_BLO + off, b_lo + ge);
    }
}

__global__ __launch_bounds__(NT_THREADS, 1)
void tc_gemm_nt(const __nv_bfloat16* __restrict__ Ahi, const __nv_bfloat16* __restrict__ Alo,
                const __nv_bfloat16* __restrict__ Bhi, const __nv_bfloat16* __restrict__ Blo,
                float* __restrict__ Cf, __nv_bfloat16* __restrict__ Chi, __nv_bfloat16* __restrict__ Clo,
                const float* __restrict__ bias, float scale, int K, int ldc,
                long sA, long sB, long sC)
{
    extern __shared__ char smem[];
    const uint32_t sbase = smem_u32(smem);
    const int tid  = threadIdx.x;
    const int lane = tid & 31;
    const int wid  = tid >> 5;
    const int warp_m = wid >> 2;      // 0..1 -> 64 rows
    const int warp_n = wid & 3;       // 0..3 -> 32 cols
    const int g = lane >> 3;          // ldmatrix tile index
    const int r = lane & 7;           // ldmatrix row-in-tile (== row&7)
    const long z = blockIdx.z;

    const __nv_bfloat16* a_hi = Ahi + z * sA + (size_t)blockIdx.y * BM * K;
    const __nv_bfloat16* a_lo = Alo + z * sA + (size_t)blockIdx.y * BM * K;
    const __nv_bfloat16* b_hi = Bhi + z * sB + (size_t)blockIdx.x * BN * K;
    const __nv_bfloat16* b_lo = Blo + z * sB + (size_t)blockIdx.x * BN * K;

    float acc[4][4][4];
    #pragma unroll
    for (int i = 0; i < 4; i++)
        #pragma unroll
        for (int j = 0; j < 4; j++)
            #pragma unroll
            for (int q = 0; q < 4; q++) acc[i][j][q] = 0.f;

    const int NKB = K / BKK;
    load_stage(sbase, a_hi, a_lo, b_hi, b_lo, K, 0, tid);
    cp_commit();

    for (int kb = 0; kb < NKB; kb++) {
        if (kb + 1 < NKB) {
            load_stage(sbase + ((kb + 1) & 1) * STAGE_BYTES,
                       a_hi, a_lo, b_hi, b_lo, K, (kb + 1) * BKK, tid);
            cp_commit();
            cp_wait1();
        } else {
            cp_wait0();
        }
        __syncthreads();

        const uint32_t st = sbase + (kb & 1) * STAGE_BYTES;
        #pragma unroll
        for (int ks = 0; ks < 4; ks++) {
            uint32_t ah[4][4], al[4][4], bh[4][2], bl[4][2];
            const int cA = ((2 * ks + (g >> 1)) ^ r) << 4;
            #pragma unroll
            for (int mi = 0; mi < 4; mi++) {
                uint32_t rowA = warp_m * 64 + mi * 16 + ((g & 1) << 3) + r;
                uint32_t addr = st + rowA * 128 + cA;
                ldsm4(ah[mi][0], ah[mi][1], ah[mi][2], ah[mi][3], addr);
                ldsm4(al[mi][0], al[mi][1], al[mi][2], al[mi][3], addr + OFF_ALO);
            }
            const int cB = ((2 * ks + (g & 1)) ^ r) << 4;
            #pragma unroll
            for (int p = 0; p < 2; p++) {
                uint32_t rowB = warp_n * 32 + ((2 * p + (g >> 1)) << 3) + r;
                uint32_t addr = st + OFF_BHI + rowB * 128 + cB;
                uint32_t t0, t1, t2, t3;
                ldsm4(t0, t1, t2, t3, addr);
                bh[2*p][0] = t0; bh[2*p][1] = t1; bh[2*p+1][0] = t2; bh[2*p+1][1] = t3;
                ldsm4(t0, t1, t2, t3, addr + 16384);
                bl[2*p][0] = t0; bl[2*p][1] = t1; bl[2*p+1][0] = t2; bl[2*p+1][1] = t3;
            }
            #pragma unroll
            for (int mi = 0; mi < 4; mi++)
                #pragma unroll
                for (int ni = 0; ni < 4; ni++) {
                    mma16816(acc[mi][ni], ah[mi], bh[ni]);
                    mma16816(acc[mi][ni], ah[mi], bl[ni]);
                    mma16816(acc[mi][ni], al[mi], bh[ni]);
                }
        }
        __syncthreads();
    }

    // ---------------- epilogue ----------------
    #pragma unroll
    for (int mi = 0; mi < 4; mi++) {
        #pragma unroll
        for (int ni = 0; ni < 4; ni++) {
            const int row0 = blockIdx.y * BM + warp_m * 64 + mi * 16 + (lane >> 2);
            const int col  = blockIdx.x * BN + warp_n * 32 + ni * 8 + 2 * (lane & 3);
            float bx = 0.f, by = 0.f;
            if (bias) { bx = __ldg(bias + col); by = __ldg(bias + col + 1); }
            #pragma unroll
            for (int h = 0; h < 2; h++) {
                float x0 = acc[mi][ni][2*h + 0] * scale + bx;
                float x1 = acc[mi][ni][2*h + 1] * scale + by;
                const size_t o = (size_t)(z * sC) + (size_t)(row0 + 8*h) * ldc + col;
                if (Cf) {
                    float2 v = make_float2(x0, x1);
                    *(float2*)&Cf[o] = v;
                }
                if (Chi) {
                    __nv_bfloat16 h0 = __float2bfloat16(x0);
                    __nv_bfloat16 h1 = __float2bfloat16(x1);
                    __nv_bfloat16 l0 = __float2bfloat16(x0 - __bfloat162float(h0));
                    __nv_bfloat16 l1 = __float2bfloat16(x1 - __bfloat162float(h1));
                    union { __nv_bfloat16 b[2]; uint32_t u; } H, L;
                    H.b[0] = h0; H.b[1] = h1; L.b[0] = l0; L.b[1] = l1;
                    *(uint32_t*)&Chi[o] = H.u;
                    *(uint32_t*)&Clo[o] = L.u;
                }
            }
        }
    }
}

// ---------------- fp32 -> bf16 hi/lo split ----------------
__global__ __launch_bounds__(256)
void split_kernel(const float* __restrict__ src, __nv_bfloat16* __restrict__ hi,
                  __nv_bfloat16* __restrict__ lo, int n)
{
    int i = (blockIdx.x * blockDim.x + threadIdx.x) * 8;
    if (i >= n) return;
    float4 v0 = *(const float4*)(src + i);
    float4 v1 = *(const float4*)(src + i + 4);
    float v[8] = {v0.x, v0.y, v0.z, v0.w, v1.x, v1.y, v1.z, v1.w};
    union { uint4 q; __nv_bfloat16 b[8]; } H, L;
    #pragma unroll
    for (int j = 0; j < 8; j++) {
        __nv_bfloat16 h = __float2bfloat16(v[j]);
        H.b[j] = h;
        L.b[j] = __float2bfloat16(v[j] - __bfloat162float(h));
    }
    *(uint4*)(hi + i) = H.q;
    *(uint4*)(lo + i) = L.q;
}

// ---------------- V transpose + split: VT[b][d][t] = V[b][t][d] ----------------
__global__ void transpose_split_kernel(const float* __restrict__ V,
                                       __nv_bfloat16* __restrict__ Th,
                                       __nv_bfloat16* __restrict__ Tl)
{
    __shared__ float tile[32][33];
    const int b = blockIdx.z;
    const float* Vb = V + (size_t)b * SS * DD;
    __nv_bfloat16* Thb = Th + (size_t)b * DD * SS;
    __nv_bfloat16* Tlb = Tl + (size_t)b * DD * SS;
    const int x = blockIdx.x * 32 + threadIdx.x;   // d
    const int y0 = blockIdx.y * 32;                // t
    #pragma unroll
    for (int i = threadIdx.y; i < 32; i += 8)
        tile[i][threadIdx.x] = Vb[(size_t)(y0 + i) * DD + x];
    __syncthreads();
    const int t = y0 + threadIdx.x;
    #pragma unroll
    for (int i = threadIdx.y; i < 32; i += 8) {
        float v = tile[threadIdx.x][i];
        __nv_bfloat16 h = __float2bfloat16(v);
        __nv_bfloat16 l = __float2bfloat16(v - __bfloat162float(h));
        size_t o = (size_t)(blockIdx.x * 32 + i) * SS + t;
        Thb[o] = h; Tlb[o] = l;
    }
}

// ---------------- per-row quantum scalars ----------------
__global__ void row_stats_kernel(const float* __restrict__ query, const float* __restrict__ key)
{
    int r = blockIdx.x * blockDim.x + threadIdx.x;
    if (r >= 2 * BSROWS) return;
    const float* x = (r < BSROWS) ? &query[(size_t)r * DD] : &key[(size_t)(r - BSROWS) * DD];
    float s = 0.f, t = 0.f;
    #pragma unroll
    for (int m = 0; m < NQ; m++) {
        float v = tanhf(x[m]);
        float a = expf(v);
        s += a; t += a * v;
    }
    if (r < BSROWS) { g_Sa[r] = s; g_Ta[r] = t; }
    else            { g_Sb[r - BSROWS] = s; g_Tb[r - BSROWS] = t; }
}

// ---------------- fused quantum + softmax (+ bf16 split of probs) ----------------
__global__ __launch_bounds__(256)
void softmax_quantum_kernel(float* __restrict__ attn_out,
                            __nv_bfloat16* __restrict__ Ph, __nv_bfloat16* __restrict__ Pl)
{
    const int row = blockIdx.x;
    const int b   = row >> 10;
    const int tid = threadIdx.x;
    const float* sc = &g_SC[(size_t)row * SS];
    const float Sa = g_Sa[row], Ta = g_Ta[row];

    __shared__ float sred[8];
    float v[4];
    float mx = -1e30f;
    #pragma unroll
    for (int u = 0; u < 4; u++) {
        int j = u * 256 + tid;
        float Sb = g_Sb[b * SS + j], Tb = g_Tb[b * SS + j];
        float Z = Sa + Sb;
        float c = sc[j] + 0.3f * (logf(Z) - (Ta + Tb) / Z);
        v[u] = c;
        mx = fmaxf(mx, c);
    }
    #pragma unroll
    for (int o = 16; o > 0; o >>= 1) mx = fmaxf(mx, __shfl_xor_sync(0xffffffffu, mx, o));
    if ((tid & 31) == 0) sred[tid >> 5] = mx;
    __syncthreads();
    if (tid == 0) {
        float x = sred[0];
        #pragma unroll
        for (int w = 1; w < 8; w++) x = fmaxf(x, sred[w]);
        sred[0] = x;
    }
    __syncthreads();
    mx = sred[0];
    __syncthreads();

    float sum = 0.f;
    #pragma unroll
    for (int u = 0; u < 4; u++) { v[u] = expf(v[u] - mx); sum += v[u]; }
    #pragma unroll
    for (int o = 16; o > 0; o >>= 1) sum += __shfl_xor_sync(0xffffffffu, sum, o);
    if ((tid & 31) == 0) sred[tid >> 5] = sum;
    __syncthreads();
    if (tid == 0) {
        float x = 0.f;
        #pragma unroll
        for (int w = 0; w < 8; w++) x += sred[w];
        sred[0] = x;
    }
    __syncthreads();
    const float inv = 1.0f / sred[0];

    #pragma unroll
    for (int u = 0; u < 4; u++) {
        int j = u * 256 + tid;
        float p = v[u] * inv;
        if (attn_out) attn_out[(size_t)row * SS + j] = p;
        __nv_bfloat16 h = __float2bfloat16(p);
        Ph[(size_t)row * SS + j] = h;
        Pl[(size_t)row * SS + j] = __float2bfloat16(p - __bfloat162float(h));
    }
}

// ---------------- launcher ----------------
#define SYMF(ptr, sym) cudaGetSymbolAddress((void**)&ptr, sym)

extern "C" void kernel_launch(void* const* d_in, const int* in_sizes, int n_in,
                              void* d_out, int out_size)
{
    const float* query = (const float*)d_in[0];
    const float* key   = (const float*)d_in[1];
    const float* value = (const float*)d_in[2];
    const float* Wq    = (const float*)d_in[3];
    const float* bq    = (const float*)d_in[4];
    const float* Wk    = (const float*)d_in[5];
    const float* bk    = (const float*)d_in[6];
    const float* Wv    = (const float*)d_in[7];
    const float* bv    = (const float*)d_in[8];
    const float* Wo    = (const float*)d_in[9];
    const float* bo    = (const float*)d_in[10];
    float* out = (float*)d_out;

    __nv_bfloat16 *qhi,*qlo,*khi,*klo,*vhi,*vlo;
    __nv_bfloat16 *wqh,*wql,*wkh,*wkl,*wvh,*wvl,*woh,*wol;
    __nv_bfloat16 *Qh,*Ql,*Kh,*Kl,*VTh,*VTl,*Ph,*Pl,*ATh,*ATl;
    float *Vp,*SCp;
    SYMF(qhi,g_qhi); SYMF(qlo,g_qlo); SYMF(khi,g_khi); SYMF(klo,g_klo);
    SYMF(vhi,g_vhi); SYMF(vlo,g_vlo);
    SYMF(wqh,g_wqhi); SYMF(wql,g_wqlo); SYMF(wkh,g_wkhi); SYMF(wkl,g_wklo);
    SYMF(wvh,g_wvhi); SYMF(wvl,g_wvlo); SYMF(woh,g_wohi); SYMF(wol,g_wolo);
    SYMF(Qh,g_Qhi); SYMF(Ql,g_Qlo); SYMF(Kh,g_Khi); SYMF(Kl,g_Klo);
    SYMF(VTh,g_VThi); SYMF(VTl,g_VTlo); SYMF(Ph,g_Phi); SYMF(Pl,g_Plo);
    SYMF(ATh,g_AThi); SYMF(ATl,g_ATlo);
    SYMF(Vp,g_V); SYMF(SCp,g_SC);

    const long OUT_N = (long)NM;
    float* attn_out = ((long)out_size >= 2 * OUT_N) ? (out + OUT_N) : nullptr;

    cudaFuncSetAttribute(tc_gemm_nt, cudaFuncAttributeMaxDynamicSharedMemorySize, SMEM_GEMM);

    // input / weight splits
    split_kernel<<<NM/2048, 256>>>(query, qhi, qlo, NM);
    split_kernel<<<NM/2048, 256>>>(key,   khi, klo, NM);
    split_kernel<<<NM/2048, 256>>>(value, vhi, vlo, NM);
    split_kernel<<<NW/2048, 256>>>(Wq, wqh, wql, NW);
    split_kernel<<<NW/2048, 256>>>(Wk, wkh, wkl, NW);
    split_kernel<<<NW/2048, 256>>>(Wv, wvh, wvl, NW);
    split_kernel<<<NW/2048, 256>>>(Wo, woh, wol, NW);

    row_stats_kernel<<<(2*BSROWS + 255)/256, 256>>>(query, key);

    dim3 gProj(DD/BN, BSROWS/BM, 1);   // (8, 32)
    dim3 gBat (SS/BN, SS/BM, BB);      // (8, 8, 4)

    // projections: X @ W^T + b
    tc_gemm_nt<<<gProj, NT_THREADS, SMEM_GEMM>>>(qhi, qlo, wqh, wql, nullptr, Qh, Ql, bq, 1.f, DD, DD, 0, 0, 0);
    tc_gemm_nt<<<gProj, NT_THREADS, SMEM_GEMM>>>(khi, klo, wkh, wkl, nullptr, Kh, Kl, bk, 1.f, DD, DD, 0, 0, 0);
    tc_gemm_nt<<<gProj, NT_THREADS, SMEM_GEMM>>>(vhi, vlo, wvh, wvl, Vp, nullptr, nullptr, bv, 1.f, DD, DD, 0, 0, 0);

    // V transpose + split (for NT attn@V)
    transpose_split_kernel<<<dim3(32,32,BB), dim3(32,8)>>>(Vp, VTh, VTl);

    // classical scores (scaled): SC[b] = CLS_SCALE * Q[b] @ K[b]^T
    tc_gemm_nt<<<gBat, NT_THREADS, SMEM_GEMM>>>(Qh, Ql, Kh, Kl, SCp, nullptr, nullptr, nullptr, CLS_SCALE,
                                                DD, SS, (long)SS*DD, (long)SS*DD, (long)SS*SS);

    // quantum + softmax -> attn (float to d_out region 2) + bf16 split
    softmax_quantum_kernel<<<BSROWS, 256>>>(attn_out, Ph, Pl);

    // attended[b] = attn[b] @ V[b]  (NT via VT)
    tc_gemm_nt<<<gBat, NT_THREADS, SMEM_GEMM>>>(Ph, Pl, VTh, VTl, nullptr, ATh, ATl, nullptr, 1.f,
                                                SS, DD, (long)SS*SS, (long)DD*SS, (long)SS*DD);

    // output = attended @ Wo^T + bo
    tc_gemm_nt<<<gProj, NT_THREADS, SMEM_GEMM>>>(ATh, ATl, woh, wol, out, nullptr, nullptr, bo, 1.f, DD, DD, 0, 0, 0);
}

// round 4
// speedup vs baseline: 2.6870x; 1.0109x over previous
#include <cuda_runtime.h>
#include <cuda_bf16.h>
#include <math.h>
#include <stdint.h>

// ---------------- problem constants ----------------
#define BB 4
#define SS 1024
#define DD 1024
#define NQ 8
#define BSROWS (BB*SS)           // 4096
#define CLS_SCALE (0.7f/128.0f)  // ALPHA / (H*sqrt(HEAD_DIM))

#define NM (BSROWS*DD)           // 4,194,304
#define NW (DD*DD)               // 1,048,576

// ---------------- scratch (device globals; 16B-aligned via uint4) ----------------
__device__ uint4 g_qhi[NM/8], g_qlo[NM/8];
__device__ uint4 g_khi[NM/8], g_klo[NM/8];
__device__ uint4 g_vhi[NM/8], g_vlo[NM/8];
__device__ uint4 g_wqhi[NW/8], g_wqlo[NW/8];
__device__ uint4 g_wkhi[NW/8], g_wklo[NW/8];
__device__ uint4 g_wvhi[NW/8], g_wvlo[NW/8];
__device__ uint4 g_wohi[NW/8], g_wolo[NW/8];
__device__ uint4 g_Qhi[NM/8],  g_Qlo[NM/8];
__device__ uint4 g_Khi[NM/8],  g_Klo[NM/8];
__device__ uint4 g_VThi[NM/8], g_VTlo[NM/8];
__device__ uint4 g_Phi[NM/8],  g_Plo[NM/8];
__device__ uint4 g_AThi[NM/8], g_ATlo[NM/8];
__device__ float g_V[NM];
__device__ float g_SC[NM];
__device__ float g_Sa[BSROWS], g_Ta[BSROWS], g_Sb[BSROWS], g_Tb[BSROWS];

// ---------------- PTX helpers (non-'a' features only) ----------------
__device__ __forceinline__ uint32_t smem_u32(const void* p) {
    uint32_t a;
    asm("{ .reg .u64 t; cvta.to.shared.u64 t, %1; cvt.u32.u64 %0, t; }" : "=r"(a) : "l"(p));
    return a;
}
__device__ __forceinline__ void cp16(uint32_t dst, const void* src) {
    asm volatile("cp.async.cg.shared.global [%0], [%1], 16;" :: "r"(dst), "l"(src) : "memory");
}
__device__ __forceinline__ void cp_commit() { asm volatile("cp.async.commit_group;" ::: "memory"); }
template<int N>
__device__ __forceinline__ void cp_wait() { asm volatile("cp.async.wait_group %0;" :: "n"(N) : "memory"); }

__device__ __forceinline__ void ldsm4(uint32_t& r0, uint32_t& r1, uint32_t& r2, uint32_t& r3,
                                      uint32_t addr) {
    asm volatile("ldmatrix.sync.aligned.m8n8.x4.shared.b16 {%0,%1,%2,%3}, [%4];"
                 : "=r"(r0), "=r"(r1), "=r"(r2), "=r"(r3) : "r"(addr));
}
__device__ __forceinline__ void mma16816(float* c, const uint32_t* a, const uint32_t* b) {
    asm volatile("mma.sync.aligned.m16n8k16.row.col.f32.bf16.bf16.f32 "
                 "{%0,%1,%2,%3}, {%4,%5,%6,%7}, {%8,%9}, {%0,%1,%2,%3};"
                 : "+f"(c[0]), "+f"(c[1]), "+f"(c[2]), "+f"(c[3])
                 : "r"(a[0]), "r"(a[1]), "r"(a[2]), "r"(a[3]), "r"(b[0]), "r"(b[1]));
}

// ---------------- HMMA GEMM: C = scale*(Ahi+Alo)@(Bhi+Blo)^T (+bias) ----------------
// Tile: BM=128 x BN=128 x BK=64. 8 warps (2x4), warp tile 64x32.
// 3-stage cp.async pipeline, register-double-buffered ldmatrix fragments.
#define BM 128
#define BN 128
#define BKK 64
#define NT_THREADS 256
#define OFF_ALO 16384
#define OFF_BHI 32768
#define OFF_BLO 49152
#define STAGE_BYTES 65536
#define NSTAGE 3
#define SMEM_GEMM (NSTAGE*STAGE_BYTES)

__device__ __forceinline__ void load_stage(
    uint32_t st, const __nv_bfloat16* a_hi, const __nv_bfloat16* a_lo,
    const __nv_bfloat16* b_hi, const __nv_bfloat16* b_lo, int K, int k0, int tid)
{
    #pragma unroll
    for (int i = 0; i < 4; i++) {
        int id = tid + i * 256;
        int r = id >> 3, c = id & 7;
        uint32_t off = (uint32_t)(r * 128 + ((c ^ (r & 7)) << 4));
        size_t ge = (size_t)r * K + k0 + c * 8;
        cp16(st + off,           a_hi + ge);
        cp16(st + OFF_ALO + off, a_lo + ge);
        cp16(st + OFF_BHI + off, b_hi + ge);
        cp16(st + OFF_BLO + off, b_lo + ge);
    }
}

struct Frag {
    uint32_t ah[4][4], al[4][4], bh[4][2], bl[4][2];
};

__device__ __forceinline__ void load_frags(Frag& f, uint32_t st, int ks,
                                           int warp_m, int warp_n, int g, int r)
{
    const int cA = ((2 * ks + (g >> 1)) ^ r) << 4;
    #pragma unroll
    for (int mi = 0; mi < 4; mi++) {
        uint32_t rowA = warp_m * 64 + mi * 16 + ((g & 1) << 3) + r;
        uint32_t addr = st + rowA * 128 + cA;
        ldsm4(f.ah[mi][0], f.ah[mi][1], f.ah[mi][2], f.ah[mi][3], addr);
        ldsm4(f.al[mi][0], f.al[mi][1], f.al[mi][2], f.al[mi][3], addr + OFF_ALO);
    }
    const int cB = ((2 * ks + (g & 1)) ^ r) << 4;
    #pragma unroll
    for (int p = 0; p < 2; p++) {
        uint32_t rowB = warp_n * 32 + ((2 * p + (g >> 1)) << 3) + r;
        uint32_t addr = st + OFF_BHI + rowB * 128 + cB;
        uint32_t t0, t1, t2, t3;
        ldsm4(t0, t1, t2, t3, addr);
        f.bh[2*p][0] = t0; f.bh[2*p][1] = t1; f.bh[2*p+1][0] = t2; f.bh[2*p+1][1] = t3;
        ldsm4(t0, t1, t2, t3, addr + 16384);
        f.bl[2*p][0] = t0; f.bl[2*p][1] = t1; f.bl[2*p+1][0] = t2; f.bl[2*p+1][1] = t3;
    }
}

__device__ __forceinline__ void do_mmas(float acc[4][4][4], const Frag& f)
{
    #pragma unroll
    for (int mi = 0; mi < 4; mi++)
        #pragma unroll
        for (int ni = 0; ni < 4; ni++) {
            mma16816(acc[mi][ni], f.ah[mi], f.bh[ni]);
            mma16816(acc[mi][ni], f.ah[mi], f.bl[ni]);
            mma16816(acc[mi][ni], f.al[mi], f.bh[ni]);
        }
}

__global__ __launch_bounds__(NT_THREADS, 1)
void tc_gemm_nt(const __nv_bfloat16* __restrict__ Ahi, const __nv_bfloat16* __restrict__ Alo,
                const __nv_bfloat16* __restrict__ Bhi, const __nv_bfloat16* __restrict__ Blo,
                float* __restrict__ Cf, __nv_bfloat16* __restrict__ Chi, __nv_bfloat16* __restrict__ Clo,
                const float* __restrict__ bias, float scale, int K, int ldc,
                long sA, long sB, long sC)
{
    extern __shared__ char smem[];
    const uint32_t sbase = smem_u32(smem);
    const int tid  = threadIdx.x;
    const int lane = tid & 31;
    const int wid  = tid >> 5;
    const int warp_m = wid >> 2;
    const int warp_n = wid & 3;
    const int g = lane >> 3;
    const int r = lane & 7;
    const long z = blockIdx.z;

    const __nv_bfloat16* a_hi = Ahi + z * sA + (size_t)blockIdx.y * BM * K;
    const __nv_bfloat16* a_lo = Alo + z * sA + (size_t)blockIdx.y * BM * K;
    const __nv_bfloat16* b_hi = Bhi + z * sB + (size_t)blockIdx.x * BN * K;
    const __nv_bfloat16* b_lo = Blo + z * sB + (size_t)blockIdx.x * BN * K;

    float acc[4][4][4];
    #pragma unroll
    for (int i = 0; i < 4; i++)
        #pragma unroll
        for (int j = 0; j < 4; j++)
            #pragma unroll
            for (int q = 0; q < 4; q++) acc[i][j][q] = 0.f;

    const int NKB = K / BKK;   // >= 8 in all uses

    // prologue: 2 stages in flight
    load_stage(sbase, a_hi, a_lo, b_hi, b_lo, K, 0, tid);
    cp_commit();
    load_stage(sbase + STAGE_BYTES, a_hi, a_lo, b_hi, b_lo, K, BKK, tid);
    cp_commit();

    Frag fr[2];
    int sidx = 0;   // smem slot of current kb

    for (int kb = 0; kb < NKB; kb++) {
        if (kb + 1 < NKB) cp_wait<1>(); else cp_wait<0>();
        __syncthreads();   // buffer kb visible to all; prior reads of slot being reloaded done

        // prefetch global for kb+2 into slot (kb+2)%3 (== slot read in iter kb-1)
        if (kb + 2 < NKB) {
            int s2 = sidx + 2; if (s2 >= NSTAGE) s2 -= NSTAGE;
            load_stage(sbase + s2 * STAGE_BYTES, a_hi, a_lo, b_hi, b_lo, K, (kb + 2) * BKK, tid);
            cp_commit();
        }

        const uint32_t st = sbase + sidx * STAGE_BYTES;
        load_frags(fr[0], st, 0, warp_m, warp_n, g, r);
        #pragma unroll
        for (int ks = 0; ks < 4; ks++) {
            if (ks < 3) load_frags(fr[(ks + 1) & 1], st, ks + 1, warp_m, warp_n, g, r);
            do_mmas(acc, fr[ks & 1]);
        }

        sidx++; if (sidx >= NSTAGE) sidx = 0;
    }

    // ---------------- epilogue ----------------
    #pragma unroll
    for (int mi = 0; mi < 4; mi++) {
        #pragma unroll
        for (int ni = 0; ni < 4; ni++) {
            const int row0 = blockIdx.y * BM + warp_m * 64 + mi * 16 + (lane >> 2);
            const int col  = blockIdx.x * BN + warp_n * 32 + ni * 8 + 2 * (lane & 3);
            float bx = 0.f, by = 0.f;
            if (bias) { bx = __ldg(bias + col); by = __ldg(bias + col + 1); }
            #pragma unroll
            for (int h = 0; h < 2; h++) {
                float x0 = acc[mi][ni][2*h + 0] * scale + bx;
                float x1 = acc[mi][ni][2*h + 1] * scale + by;
                const size_t o = (size_t)(z * sC) + (size_t)(row0 + 8*h) * ldc + col;
                if (Cf) {
                    float2 v = make_float2(x0, x1);
                    *(float2*)&Cf[o] = v;
                }
                if (Chi) {
                    __nv_bfloat16 h0 = __float2bfloat16(x0);
                    __nv_bfloat16 h1 = __float2bfloat16(x1);
                    __nv_bfloat16 l0 = __float2bfloat16(x0 - __bfloat162float(h0));
                    __nv_bfloat16 l1 = __float2bfloat16(x1 - __bfloat162float(h1));
                    union { __nv_bfloat16 b[2]; uint32_t u; } H, L;
                    H.b[0] = h0; H.b[1] = h1; L.b[0] = l0; L.b[1] = l1;
                    *(uint32_t*)&Chi[o] = H.u;
                    *(uint32_t*)&Clo[o] = L.u;
                }
            }
        }
    }
}

// ---------------- fp32 -> bf16 hi/lo split ----------------
__global__ __launch_bounds__(256)
void split_kernel(const float* __restrict__ src, __nv_bfloat16* __restrict__ hi,
                  __nv_bfloat16* __restrict__ lo, int n)
{
    int i = (blockIdx.x * blockDim.x + threadIdx.x) * 8;
    if (i >= n) return;
    float4 v0 = *(const float4*)(src + i);
    float4 v1 = *(const float4*)(src + i + 4);
    float v[8] = {v0.x, v0.y, v0.z, v0.w, v1.x, v1.y, v1.z, v1.w};
    union { uint4 q; __nv_bfloat16 b[8]; } H, L;
    #pragma unroll
    for (int j = 0; j < 8; j++) {
        __nv_bfloat16 h = __float2bfloat16(v[j]);
        H.b[j] = h;
        L.b[j] = __float2bfloat16(v[j] - __bfloat162float(h));
    }
    *(uint4*)(hi + i) = H.q;
    *(uint4*)(lo + i) = L.q;
}

// ---------------- V transpose + split ----------------
__global__ void transpose_split_kernel(const float* __restrict__ V,
                                       __nv_bfloat16* __restrict__ Th,
                                       __nv_bfloat16* __restrict__ Tl)
{
    __shared__ float tile[32][33];
    const int b = blockIdx.z;
    const float* Vb = V + (size_t)b * SS * DD;
    __nv_bfloat16* Thb = Th + (size_t)b * DD * SS;
    __nv_bfloat16* Tlb = Tl + (size_t)b * DD * SS;
    const int x = blockIdx.x * 32 + threadIdx.x;
    const int y0 = blockIdx.y * 32;
    #pragma unroll
    for (int i = threadIdx.y; i < 32; i += 8)
        tile[i][threadIdx.x] = Vb[(size_t)(y0 + i) * DD + x];
    __syncthreads();
    const int t = y0 + threadIdx.x;
    #pragma unroll
    for (int i = threadIdx.y; i < 32; i += 8) {
        float v = tile[threadIdx.x][i];
        __nv_bfloat16 h = __float2bfloat16(v);
        __nv_bfloat16 l = __float2bfloat16(v - __bfloat162float(h));
        size_t o = (size_t)(blockIdx.x * 32 + i) * SS + t;
        Thb[o] = h; Tlb[o] = l;
    }
}

// ---------------- per-row quantum scalars ----------------
__global__ void row_stats_kernel(const float* __restrict__ query, const float* __restrict__ key)
{
    int r = blockIdx.x * blockDim.x + threadIdx.x;
    if (r >= 2 * BSROWS) return;
    const float* x = (r < BSROWS) ? &query[(size_t)r * DD] : &key[(size_t)(r - BSROWS) * DD];
    float s = 0.f, t = 0.f;
    #pragma unroll
    for (int m = 0; m < NQ; m++) {
        float v = tanhf(x[m]);
        float a = expf(v);
        s += a; t += a * v;
    }
    if (r < BSROWS) { g_Sa[r] = s; g_Ta[r] = t; }
    else            { g_Sb[r - BSROWS] = s; g_Tb[r - BSROWS] = t; }
}

// ---------------- fused quantum + softmax (+ bf16 split of probs) ----------------
__global__ __launch_bounds__(256)
void softmax_quantum_kernel(float* __restrict__ attn_out,
                            __nv_bfloat16* __restrict__ Ph, __nv_bfloat16* __restrict__ Pl)
{
    const int row = blockIdx.x;
    const int b   = row >> 10;
    const int tid = threadIdx.x;
    const float* sc = &g_SC[(size_t)row * SS];
    const float Sa = g_Sa[row], Ta = g_Ta[row];

    __shared__ float sred[8];
    float v[4];
    float mx = -1e30f;
    #pragma unroll
    for (int u = 0; u < 4; u++) {
        int j = u * 256 + tid;
        float Sb = g_Sb[b * SS + j], Tb = g_Tb[b * SS + j];
        float Z = Sa + Sb;
        float c = sc[j] + 0.3f * (logf(Z) - (Ta + Tb) / Z);
        v[u] = c;
        mx = fmaxf(mx, c);
    }
    #pragma unroll
    for (int o = 16; o > 0; o >>= 1) mx = fmaxf(mx, __shfl_xor_sync(0xffffffffu, mx, o));
    if ((tid & 31) == 0) sred[tid >> 5] = mx;
    __syncthreads();
    if (tid == 0) {
        float x = sred[0];
        #pragma unroll
        for (int w = 1; w < 8; w++) x = fmaxf(x, sred[w]);
        sred[0] = x;
    }
    __syncthreads();
    mx = sred[0];
    __syncthreads();

    float sum = 0.f;
    #pragma unroll
    for (int u = 0; u < 4; u++) { v[u] = expf(v[u] - mx); sum += v[u]; }
    #pragma unroll
    for (int o = 16; o > 0; o >>= 1) sum += __shfl_xor_sync(0xffffffffu, sum, o);
    if ((tid & 31) == 0) sred[tid >> 5] = sum;
    __syncthreads();
    if (tid == 0) {
        float x = 0.f;
        #pragma unroll
        for (int w = 0; w < 8; w++) x += sred[w];
        sred[0] = x;
    }
    __syncthreads();
    const float inv = 1.0f / sred[0];

    #pragma unroll
    for (int u = 0; u < 4; u++) {
        int j = u * 256 + tid;
        float p = v[u] * inv;
        if (attn_out) attn_out[(size_t)row * SS + j] = p;
        __nv_bfloat16 h = __float2bfloat16(p);
        Ph[(size_t)row * SS + j] = h;
        Pl[(size_t)row * SS + j] = __float2bfloat16(p - __bfloat162float(h));
    }
}

// ---------------- launcher ----------------
#define SYMF(ptr, sym) cudaGetSymbolAddress((void**)&ptr, sym)

extern "C" void kernel_launch(void* const* d_in, const int* in_sizes, int n_in,
                              void* d_out, int out_size)
{
    const float* query = (const float*)d_in[0];
    const float* key   = (const float*)d_in[1];
    const float* value = (const float*)d_in[2];
    const float* Wq    = (const float*)d_in[3];
    const float* bq    = (const float*)d_in[4];
    const float* Wk    = (const float*)d_in[5];
    const float* bk    = (const float*)d_in[6];
    const float* Wv    = (const float*)d_in[7];
    const float* bv    = (const float*)d_in[8];
    const float* Wo    = (const float*)d_in[9];
    const float* bo    = (const float*)d_in[10];
    float* out = (float*)d_out;

    __nv_bfloat16 *qhi,*qlo,*khi,*klo,*vhi,*vlo;
    __nv_bfloat16 *wqh,*wql,*wkh,*wkl,*wvh,*wvl,*woh,*wol;
    __nv_bfloat16 *Qh,*Ql,*Kh,*Kl,*VTh,*VTl,*Ph,*Pl,*ATh,*ATl;
    float *Vp,*SCp;
    SYMF(qhi,g_qhi); SYMF(qlo,g_qlo); SYMF(khi,g_khi); SYMF(klo,g_klo);
    SYMF(vhi,g_vhi); SYMF(vlo,g_vlo);
    SYMF(wqh,g_wqhi); SYMF(wql,g_wqlo); SYMF(wkh,g_wkhi); SYMF(wkl,g_wklo);
    SYMF(wvh,g_wvhi); SYMF(wvl,g_wvlo); SYMF(woh,g_wohi); SYMF(wol,g_wolo);
    SYMF(Qh,g_Qhi); SYMF(Ql,g_Qlo); SYMF(Kh,g_Khi); SYMF(Kl,g_Klo);
    SYMF(VTh,g_VThi); SYMF(VTl,g_VTlo); SYMF(Ph,g_Phi); SYMF(Pl,g_Plo);
    SYMF(ATh,g_AThi); SYMF(ATl,g_ATlo);
    SYMF(Vp,g_V); SYMF(SCp,g_SC);

    const long OUT_N = (long)NM;
    float* attn_out = ((long)out_size >= 2 * OUT_N) ? (out + OUT_N) : nullptr;

    cudaFuncSetAttribute(tc_gemm_nt, cudaFuncAttributeMaxDynamicSharedMemorySize, SMEM_GEMM);

    dim3 gProj(DD/BN, BSROWS/BM, 1);   // (8, 32)
    dim3 gBat (SS/BN, SS/BM, BB);      // (8, 8, 4)

    // launches 1-5 (ncu -s 5 skips these)
    split_kernel<<<NM/2048, 256>>>(query, qhi, qlo, NM);
    split_kernel<<<NM/2048, 256>>>(key,   khi, klo, NM);
    split_kernel<<<NM/2048, 256>>>(value, vhi, vlo, NM);
    split_kernel<<<NW/2048, 256>>>(Wq, wqh, wql, NW);
    row_stats_kernel<<<(2*BSROWS + 255)/256, 256>>>(query, key);

    // launch 6: profiled by ncu
    tc_gemm_nt<<<gProj, NT_THREADS, SMEM_GEMM>>>(qhi, qlo, wqh, wql, nullptr, Qh, Ql, bq, 1.f, DD, DD, 0, 0, 0);

    split_kernel<<<NW/2048, 256>>>(Wk, wkh, wkl, NW);
    tc_gemm_nt<<<gProj, NT_THREADS, SMEM_GEMM>>>(khi, klo, wkh, wkl, nullptr, Kh, Kl, bk, 1.f, DD, DD, 0, 0, 0);

    split_kernel<<<NW/2048, 256>>>(Wv, wvh, wvl, NW);
    tc_gemm_nt<<<gProj, NT_THREADS, SMEM_GEMM>>>(vhi, vlo, wvh, wvl, Vp, nullptr, nullptr, bv, 1.f, DD, DD, 0, 0, 0);

    transpose_split_kernel<<<dim3(32,32,BB), dim3(32,8)>>>(Vp, VTh, VTl);
    split_kernel<<<NW/2048, 256>>>(Wo, woh, wol, NW);

    // classical scores (scaled)
    tc_gemm_nt<<<gBat, NT_THREADS, SMEM_GEMM>>>(Qh, Ql, Kh, Kl, SCp, nullptr, nullptr, nullptr, CLS_SCALE,
                                                DD, SS, (long)SS*DD, (long)SS*DD, (long)SS*SS);

    // quantum + softmax
    softmax_quantum_kernel<<<BSROWS, 256>>>(attn_out, Ph, Pl);

    // attended = attn @ V (NT via VT)
    tc_gemm_nt<<<gBat, NT_THREADS, SMEM_GEMM>>>(Ph, Pl, VTh, VTl, nullptr, ATh, ATl, nullptr, 1.f,
                                                SS, DD, (long)SS*SS, (long)DD*SS, (long)SS*DD);

    // output projection
    tc_gemm_nt<<<gProj, NT_THREADS, SMEM_GEMM>>>(ATh, ATl, woh, wol, out, nullptr, nullptr, bo, 1.f, DD, DD, 0, 0, 0);
}

// round 5
// speedup vs baseline: 5.9522x; 2.2151x over previous
#include <cuda_runtime.h>
#include <cuda_fp16.h>
#include <math.h>
#include <stdint.h>

// ---------------- problem constants ----------------
#define BB 4
#define SS 1024
#define DD 1024
#define NQ 8
#define BSROWS (BB*SS)           // 4096
#define CLS_SCALE (0.7f/128.0f)  // ALPHA / (H*sqrt(HEAD_DIM))

#define NM (BSROWS*DD)           // 4,194,304
#define NW (DD*DD)               // 1,048,576

// ---------------- scratch (device globals; 16B-aligned via uint4) ----------------
__device__ uint4 g_qh[NM/8], g_kh[NM/8], g_vh[NM/8];
__device__ uint4 g_wqh[NW/8], g_wkh[NW/8], g_wvh[NW/8], g_woh[NW/8];
__device__ uint4 g_Qh[NM/8], g_Kh[NM/8], g_Vh[NM/8], g_VTh[NM/8];
__device__ uint4 g_Ph[NM/8], g_ATh[NM/8];
__device__ float g_SC[NM];
__device__ float g_Sa[BSROWS], g_Ta[BSROWS], g_Sb[BSROWS], g_Tb[BSROWS];

// ---------------- PTX helpers (non-'a' features only) ----------------
__device__ __forceinline__ uint32_t smem_u32(const void* p) {
    uint32_t a;
    asm("{ .reg .u64 t; cvta.to.shared.u64 t, %1; cvt.u32.u64 %0, t; }" : "=r"(a) : "l"(p));
    return a;
}
__device__ __forceinline__ void cp16(uint32_t dst, const void* src) {
    asm volatile("cp.async.cg.shared.global [%0], [%1], 16;" :: "r"(dst), "l"(src) : "memory");
}
__device__ __forceinline__ void cp_commit() { asm volatile("cp.async.commit_group;" ::: "memory"); }
template<int N>
__device__ __forceinline__ void cp_wait() { asm volatile("cp.async.wait_group %0;" :: "n"(N) : "memory"); }

__device__ __forceinline__ void ldsm4(uint32_t& r0, uint32_t& r1, uint32_t& r2, uint32_t& r3,
                                      uint32_t addr) {
    asm volatile("ldmatrix.sync.aligned.m8n8.x4.shared.b16 {%0,%1,%2,%3}, [%4];"
                 : "=r"(r0), "=r"(r1), "=r"(r2), "=r"(r3) : "r"(addr));
}
__device__ __forceinline__ void mma16816(float* c, const uint32_t* a, const uint32_t* b) {
    asm volatile("mma.sync.aligned.m16n8k16.row.col.f32.f16.f16.f32 "
                 "{%0,%1,%2,%3}, {%4,%5,%6,%7}, {%8,%9}, {%0,%1,%2,%3};"
                 : "+f"(c[0]), "+f"(c[1]), "+f"(c[2]), "+f"(c[3])
                 : "r"(a[0]), "r"(a[1]), "r"(a[2]), "r"(a[3]), "r"(b[0]), "r"(b[1]));
}

// ---------------- fp16 HMMA GEMM: C = scale*A@B^T (+bias) ----------------
// A: [M,K] row-major fp16. B: [N,K] row-major fp16 (NT). Tile 128x128x64,
// 8 warps (2x4), warp tile 64x32, 3-stage cp.async, 2 CTAs/SM.
#define BM 128
#define BN 128
#define BKK 64
#define NT_THREADS 256
#define OFF_B 16384
#define STAGE_BYTES 32768
#define NSTAGE 3
#define SMEM_GEMM (NSTAGE*STAGE_BYTES)

__device__ __forceinline__ void load_stage(
    uint32_t st, const __half* a, const __half* b, int K, int k0, int tid)
{
    #pragma unroll
    for (int i = 0; i < 4; i++) {
        int id = tid + i * 256;
        int r = id >> 3, c = id & 7;
        uint32_t off = (uint32_t)(r * 128 + ((c ^ (r & 7)) << 4));
        size_t ge = (size_t)r * K + k0 + c * 8;
        cp16(st + off,         a + ge);
        cp16(st + OFF_B + off, b + ge);
    }
}

__global__ __launch_bounds__(NT_THREADS, 2)
void tc_gemm_nt(const __half* __restrict__ A, const __half* __restrict__ B,
                float* __restrict__ Cf, __half* __restrict__ Ch,
                const float* __restrict__ bias, float scale, int K, int ldc,
                long sA, long sB, long sC)
{
    extern __shared__ char smem[];
    const uint32_t sbase = smem_u32(smem);
    const int tid  = threadIdx.x;
    const int lane = tid & 31;
    const int wid  = tid >> 5;
    const int warp_m = wid >> 2;
    const int warp_n = wid & 3;
    const int g = lane >> 3;
    const int r = lane & 7;
    const long z = blockIdx.z;

    const __half* a_p = A + z * sA + (size_t)blockIdx.y * BM * K;
    const __half* b_p = B + z * sB + (size_t)blockIdx.x * BN * K;

    float acc[4][4][4];
    #pragma unroll
    for (int i = 0; i < 4; i++)
        #pragma unroll
        for (int j = 0; j < 4; j++)
            #pragma unroll
            for (int q = 0; q < 4; q++) acc[i][j][q] = 0.f;

    const int NKB = K / BKK;   // 16

    load_stage(sbase, a_p, b_p, K, 0, tid);
    cp_commit();
    load_stage(sbase + STAGE_BYTES, a_p, b_p, K, BKK, tid);
    cp_commit();

    int sidx = 0;
    for (int kb = 0; kb < NKB; kb++) {
        if (kb + 1 < NKB) cp_wait<1>(); else cp_wait<0>();
        __syncthreads();

        if (kb + 2 < NKB) {
            int s2 = sidx + 2; if (s2 >= NSTAGE) s2 -= NSTAGE;
            load_stage(sbase + s2 * STAGE_BYTES, a_p, b_p, K, (kb + 2) * BKK, tid);
            cp_commit();
        }

        const uint32_t st = sbase + sidx * STAGE_BYTES;
        #pragma unroll
        for (int ks = 0; ks < 4; ks++) {
            uint32_t ah[4][4], bh[4][2];
            const int cA = ((2 * ks + (g >> 1)) ^ r) << 4;
            #pragma unroll
            for (int mi = 0; mi < 4; mi++) {
                uint32_t rowA = warp_m * 64 + mi * 16 + ((g & 1) << 3) + r;
                ldsm4(ah[mi][0], ah[mi][1], ah[mi][2], ah[mi][3], st + rowA * 128 + cA);
            }
            const int cB = ((2 * ks + (g & 1)) ^ r) << 4;
            #pragma unroll
            for (int p = 0; p < 2; p++) {
                uint32_t rowB = warp_n * 32 + ((2 * p + (g >> 1)) << 3) + r;
                uint32_t t0, t1, t2, t3;
                ldsm4(t0, t1, t2, t3, st + OFF_B + rowB * 128 + cB);
                bh[2*p][0] = t0; bh[2*p][1] = t1; bh[2*p+1][0] = t2; bh[2*p+1][1] = t3;
            }
            #pragma unroll
            for (int mi = 0; mi < 4; mi++)
                #pragma unroll
                for (int ni = 0; ni < 4; ni++)
                    mma16816(acc[mi][ni], ah[mi], bh[ni]);
        }
        sidx++; if (sidx >= NSTAGE) sidx = 0;
    }

    // ---------------- epilogue ----------------
    #pragma unroll
    for (int mi = 0; mi < 4; mi++) {
        #pragma unroll
        for (int ni = 0; ni < 4; ni++) {
            const int row0 = blockIdx.y * BM + warp_m * 64 + mi * 16 + (lane >> 2);
            const int col  = blockIdx.x * BN + warp_n * 32 + ni * 8 + 2 * (lane & 3);
            float bx = 0.f, by = 0.f;
            if (bias) { bx = __ldg(bias + col); by = __ldg(bias + col + 1); }
            #pragma unroll
            for (int h = 0; h < 2; h++) {
                float x0 = acc[mi][ni][2*h + 0] * scale + bx;
                float x1 = acc[mi][ni][2*h + 1] * scale + by;
                const size_t o = (size_t)(z * sC) + (size_t)(row0 + 8*h) * ldc + col;
                if (Cf) *(float2*)&Cf[o] = make_float2(x0, x1);
                if (Ch) {
                    union { __half b[2]; uint32_t u; } H;
                    H.b[0] = __float2half(x0); H.b[1] = __float2half(x1);
                    *(uint32_t*)&Ch[o] = H.u;
                }
            }
        }
    }
}

// ---------------- fp32 -> fp16 convert ----------------
__global__ __launch_bounds__(256)
void conv_kernel(const float* __restrict__ src, __half* __restrict__ dst, int n)
{
    int i = (blockIdx.x * blockDim.x + threadIdx.x) * 8;
    if (i >= n) return;
    float4 v0 = *(const float4*)(src + i);
    float4 v1 = *(const float4*)(src + i + 4);
    float v[8] = {v0.x, v0.y, v0.z, v0.w, v1.x, v1.y, v1.z, v1.w};
    union { uint4 q; __half b[8]; } H;
    #pragma unroll
    for (int j = 0; j < 8; j++) H.b[j] = __float2half(v[j]);
    *(uint4*)(dst + i) = H.q;
}

// ---------------- fp16 transpose: VT[b][d][t] = V[b][t][d] ----------------
__global__ void transpose_h_kernel(const __half* __restrict__ V, __half* __restrict__ T)
{
    __shared__ __half tile[32][33];
    const int b = blockIdx.z;
    const __half* Vb = V + (size_t)b * SS * DD;
    __half* Tb = T + (size_t)b * DD * SS;
    const int x = blockIdx.x * 32 + threadIdx.x;   // d
    const int y0 = blockIdx.y * 32;                // t
    #pragma unroll
    for (int i = threadIdx.y; i < 32; i += 8)
        tile[i][threadIdx.x] = Vb[(size_t)(y0 + i) * DD + x];
    __syncthreads();
    const int t = y0 + threadIdx.x;
    #pragma unroll
    for (int i = threadIdx.y; i < 32; i += 8)
        Tb[(size_t)(blockIdx.x * 32 + i) * SS + t] = tile[threadIdx.x][i];
}

// ---------------- per-row quantum scalars ----------------
__global__ void row_stats_kernel(const float* __restrict__ query, const float* __restrict__ key)
{
    int r = blockIdx.x * blockDim.x + threadIdx.x;
    if (r >= 2 * BSROWS) return;
    const float* x = (r < BSROWS) ? &query[(size_t)r * DD] : &key[(size_t)(r - BSROWS) * DD];
    float s = 0.f, t = 0.f;
    #pragma unroll
    for (int m = 0; m < NQ; m++) {
        float v = tanhf(x[m]);
        float a = expf(v);
        s += a; t += a * v;
    }
    if (r < BSROWS) { g_Sa[r] = s; g_Ta[r] = t; }
    else            { g_Sb[r - BSROWS] = s; g_Tb[r - BSROWS] = t; }
}

// ---------------- fused quantum + softmax (fp32 attn out + fp16 P) ----------------
__global__ __launch_bounds__(256)
void softmax_quantum_kernel(float* __restrict__ attn_out, __half* __restrict__ Ph)
{
    const int row = blockIdx.x;
    const int b   = row >> 10;
    const int tid = threadIdx.x;
    const float* sc = &g_SC[(size_t)row * SS];
    const float Sa = g_Sa[row], Ta = g_Ta[row];

    __shared__ float sred[8];
    float v[4];
    float mx = -1e30f;
    #pragma unroll
    for (int u = 0; u < 4; u++) {
        int j = u * 256 + tid;
        float Sb = g_Sb[b * SS + j], Tb = g_Tb[b * SS + j];
        float Z = Sa + Sb;
        float c = sc[j] + 0.3f * (logf(Z) - (Ta + Tb) / Z);
        v[u] = c;
        mx = fmaxf(mx, c);
    }
    #pragma unroll
    for (int o = 16; o > 0; o >>= 1) mx = fmaxf(mx, __shfl_xor_sync(0xffffffffu, mx, o));
    if ((tid & 31) == 0) sred[tid >> 5] = mx;
    __syncthreads();
    if (tid == 0) {
        float x = sred[0];
        #pragma unroll
        for (int w = 1; w < 8; w++) x = fmaxf(x, sred[w]);
        sred[0] = x;
    }
    __syncthreads();
    mx = sred[0];
    __syncthreads();

    float sum = 0.f;
    #pragma unroll
    for (int u = 0; u < 4; u++) { v[u] = expf(v[u] - mx); sum += v[u]; }
    #pragma unroll
    for (int o = 16; o > 0; o >>= 1) sum += __shfl_xor_sync(0xffffffffu, sum, o);
    if ((tid & 31) == 0) sred[tid >> 5] = sum;
    __syncthreads();
    if (tid == 0) {
        float x = 0.f;
        #pragma unroll
        for (int w = 0; w < 8; w++) x += sred[w];
        sred[0] = x;
    }
    __syncthreads();
    const float inv = 1.0f / sred[0];

    #pragma unroll
    for (int u = 0; u < 4; u++) {
        int j = u * 256 + tid;
        float p = v[u] * inv;
        if (attn_out) attn_out[(size_t)row * SS + j] = p;
        Ph[(size_t)row * SS + j] = __float2half(p);
    }
}

// ---------------- launcher ----------------
#define SYMF(ptr, sym) cudaGetSymbolAddress((void**)&ptr, sym)

extern "C" void kernel_launch(void* const* d_in, const int* in_sizes, int n_in,
                              void* d_out, int out_size)
{
    const float* query = (const float*)d_in[0];
    const float* key   = (const float*)d_in[1];
    const float* value = (const float*)d_in[2];
    const float* Wq    = (const float*)d_in[3];
    const float* bq    = (const float*)d_in[4];
    const float* Wk    = (const float*)d_in[5];
    const float* bk    = (const float*)d_in[6];
    const float* Wv    = (const float*)d_in[7];
    const float* bv    = (const float*)d_in[8];
    const float* Wo    = (const float*)d_in[9];
    const float* bo    = (const float*)d_in[10];
    float* out = (float*)d_out;

    __half *qh,*kh,*vh,*wqh,*wkh,*wvh,*woh;
    __half *Qh,*Kh,*Vh,*VTh,*Ph,*ATh;
    float *SCp;
    SYMF(qh,g_qh); SYMF(kh,g_kh); SYMF(vh,g_vh);
    SYMF(wqh,g_wqh); SYMF(wkh,g_wkh); SYMF(wvh,g_wvh); SYMF(woh,g_woh);
    SYMF(Qh,g_Qh); SYMF(Kh,g_Kh); SYMF(Vh,g_Vh); SYMF(VTh,g_VTh);
    SYMF(Ph,g_Ph); SYMF(ATh,g_ATh);
    SYMF(SCp,g_SC);

    const long OUT_N = (long)NM;
    float* attn_out = ((long)out_size >= 2 * OUT_N) ? (out + OUT_N) : nullptr;

    cudaFuncSetAttribute(tc_gemm_nt, cudaFuncAttributeMaxDynamicSharedMemorySize, SMEM_GEMM);

    dim3 gProj(DD/BN, BSROWS/BM, 1);   // (8, 32)
    dim3 gBat (SS/BN, SS/BM, BB);      // (8, 8, 4)

    // launches 1-5
    conv_kernel<<<NM/2048, 256>>>(query, qh, NM);
    conv_kernel<<<NM/2048, 256>>>(key,   kh, NM);
    conv_kernel<<<NM/2048, 256>>>(value, vh, NM);
    conv_kernel<<<NW/2048, 256>>>(Wq, wqh, NW);
    row_stats_kernel<<<(2*BSROWS + 255)/256, 256>>>(query, key);

    // launch 6: profiled by ncu (-s 5 -c 1)
    tc_gemm_nt<<<gProj, NT_THREADS, SMEM_GEMM>>>(qh, wqh, nullptr, Qh, bq, 1.f, DD, DD, 0, 0, 0);

    conv_kernel<<<NW/2048, 256>>>(Wk, wkh, NW);
    tc_gemm_nt<<<gProj, NT_THREADS, SMEM_GEMM>>>(kh, wkh, nullptr, Kh, bk, 1.f, DD, DD, 0, 0, 0);

    conv_kernel<<<NW/2048, 256>>>(Wv, wvh, NW);
    tc_gemm_nt<<<gProj, NT_THREADS, SMEM_GEMM>>>(vh, wvh, nullptr, Vh, bv, 1.f, DD, DD, 0, 0, 0);

    transpose_h_kernel<<<dim3(32,32,BB), dim3(32,8)>>>(Vh, VTh);
    conv_kernel<<<NW/2048, 256>>>(Wo, woh, NW);

    // classical scores (scaled)
    tc_gemm_nt<<<gBat, NT_THREADS, SMEM_GEMM>>>(Qh, Kh, SCp, nullptr, nullptr, CLS_SCALE,
                                                DD, SS, (long)SS*DD, (long)SS*DD, (long)SS*SS);

    // quantum + softmax
    softmax_quantum_kernel<<<BSROWS, 256>>>(attn_out, Ph);

    // attended = attn @ V (NT via VT)
    tc_gemm_nt<<<gBat, NT_THREADS, SMEM_GEMM>>>(Ph, VTh, nullptr, ATh, nullptr, 1.f,
                                                SS, DD, (long)SS*SS, (long)DD*SS, (long)SS*DD);

    // output projection
    tc_gemm_nt<<<gProj, NT_THREADS, SMEM_GEMM>>>(ATh, woh, out, nullptr, bo, 1.f, DD, DD, 0, 0, 0);
}

// round 6
// speedup vs baseline: 6.1823x; 1.0387x over previous
#include <cuda_runtime.h>
#include <cuda_fp16.h>
#include <math.h>
#include <stdint.h>

// ---------------- problem constants ----------------
#define BB 4
#define SS 1024
#define DD 1024
#define NQ 8
#define BSROWS (BB*SS)           // 4096
#define CLS_SCALE (0.7f/128.0f)  // ALPHA / (H*sqrt(HEAD_DIM))

#define NM (BSROWS*DD)           // 4,194,304
#define NW (DD*DD)               // 1,048,576

// ---------------- scratch (device globals) ----------------
__device__ uint4 g_qh[NM/8], g_kh[NM/8], g_vh[NM/8];
__device__ uint4 g_wh[4][NW/8];                  // Wq, Wk, Wv, Wo fp16
__device__ uint4 g_Qh[NM/8], g_Kh[NM/8], g_Vh[NM/8], g_VTh[NM/8];
__device__ uint4 g_Ph[NM/8], g_ATh[NM/8];
__device__ float g_SC[NM];
__device__ float g_Sa[BSROWS], g_Ta[BSROWS], g_Sb[BSROWS], g_Tb[BSROWS];

// ---------------- lookup tables (quantum log/rcp + softmax exp) ----------------
#define TBL_N   4096
#define TBL_Z0  5.5f
#define TBL_Z1  44.0f
#define TBL_E0  -33.0f
__device__ float4 g_tblZ[TBL_N];    // (ln, dln, rcp, drcp) per node
__device__ float2 g_tblE[TBL_N];    // (exp, dexp) per node

__global__ void build_tables_kernel()
{
    int k = blockIdx.x * blockDim.x + threadIdx.x;
    if (k >= TBL_N) return;
    const float hz = (TBL_Z1 - TBL_Z0) / TBL_N;
    float z0 = TBL_Z0 + k * hz, z1 = z0 + hz;
    float l0 = logf(z0), l1 = logf(z1);
    float r0 = 1.0f / z0,  r1 = 1.0f / z1;
    g_tblZ[k] = make_float4(l0, (l1 - l0) / hz, r0, (r1 - r0) / hz);
    const float he = (0.0f - TBL_E0) / TBL_N;
    float x0 = TBL_E0 + k * he, x1 = x0 + he;
    float e0 = expf(x0), e1 = expf(x1);
    g_tblE[k] = make_float2(e0, (e1 - e0) / he);
}

// ---------------- PTX helpers (non-'a' features only) ----------------
__device__ __forceinline__ uint32_t smem_u32(const void* p) {
    uint32_t a;
    asm("{ .reg .u64 t; cvta.to.shared.u64 t, %1; cvt.u32.u64 %0, t; }" : "=r"(a) : "l"(p));
    return a;
}
__device__ __forceinline__ void cp16(uint32_t dst, const void* src) {
    asm volatile("cp.async.cg.shared.global [%0], [%1], 16;" :: "r"(dst), "l"(src) : "memory");
}
__device__ __forceinline__ void cp_commit() { asm volatile("cp.async.commit_group;" ::: "memory"); }
template<int N>
__device__ __forceinline__ void cp_wait() { asm volatile("cp.async.wait_group %0;" :: "n"(N) : "memory"); }

__device__ __forceinline__ void ldsm4(uint32_t& r0, uint32_t& r1, uint32_t& r2, uint32_t& r3,
                                      uint32_t addr) {
    asm volatile("ldmatrix.sync.aligned.m8n8.x4.shared.b16 {%0,%1,%2,%3}, [%4];"
                 : "=r"(r0), "=r"(r1), "=r"(r2), "=r"(r3) : "r"(addr));
}
__device__ __forceinline__ void mma16816(float* c, const uint32_t* a, const uint32_t* b) {
    asm volatile("mma.sync.aligned.m16n8k16.row.col.f32.f16.f16.f32 "
                 "{%0,%1,%2,%3}, {%4,%5,%6,%7}, {%8,%9}, {%0,%1,%2,%3};"
                 : "+f"(c[0]), "+f"(c[1]), "+f"(c[2]), "+f"(c[3])
                 : "r"(a[0]), "r"(a[1]), "r"(a[2]), "r"(a[3]), "r"(b[0]), "r"(b[1]));
}

// ---------------- fp16 HMMA GEMM: C = scale*A@B^T (+bias) ----------------
#define BM 128
#define BN 128
#define BKK 64
#define NT_THREADS 256
#define OFF_B 16384
#define STAGE_BYTES 32768
#define NSTAGE 3
#define SMEM_GEMM (NSTAGE*STAGE_BYTES)

__device__ __forceinline__ void load_stage(
    uint32_t st, const __half* a, const __half* b, int K, int k0, int tid)
{
    #pragma unroll
    for (int i = 0; i < 4; i++) {
        int id = tid + i * 256;
        int r = id >> 3, c = id & 7;
        uint32_t off = (uint32_t)(r * 128 + ((c ^ (r & 7)) << 4));
        size_t ge = (size_t)r * K + k0 + c * 8;
        cp16(st + off,         a + ge);
        cp16(st + OFF_B + off, b + ge);
    }
}

__global__ __launch_bounds__(NT_THREADS, 2)
void tc_gemm_nt(const __half* __restrict__ A, const __half* __restrict__ B,
                float* __restrict__ Cf, __half* __restrict__ Ch,
                const float* __restrict__ bias, float scale, int K, int ldc,
                long sA, long sB, long sC)
{
    extern __shared__ char smem[];
    const uint32_t sbase = smem_u32(smem);
    const int tid  = threadIdx.x;
    const int lane = tid & 31;
    const int wid  = tid >> 5;
    const int warp_m = wid >> 2;
    const int warp_n = wid & 3;
    const int g = lane >> 3;
    const int r = lane & 7;
    const long z = blockIdx.z;

    const __half* a_p = A + z * sA + (size_t)blockIdx.y * BM * K;
    const __half* b_p = B + z * sB + (size_t)blockIdx.x * BN * K;

    float acc[4][4][4];
    #pragma unroll
    for (int i = 0; i < 4; i++)
        #pragma unroll
        for (int j = 0; j < 4; j++)
            #pragma unroll
            for (int q = 0; q < 4; q++) acc[i][j][q] = 0.f;

    const int NKB = K / BKK;

    load_stage(sbase, a_p, b_p, K, 0, tid);
    cp_commit();
    load_stage(sbase + STAGE_BYTES, a_p, b_p, K, BKK, tid);
    cp_commit();

    int sidx = 0;
    for (int kb = 0; kb < NKB; kb++) {
        if (kb + 1 < NKB) cp_wait<1>(); else cp_wait<0>();
        __syncthreads();

        if (kb + 2 < NKB) {
            int s2 = sidx + 2; if (s2 >= NSTAGE) s2 -= NSTAGE;
            load_stage(sbase + s2 * STAGE_BYTES, a_p, b_p, K, (kb + 2) * BKK, tid);
            cp_commit();
        }

        const uint32_t st = sbase + sidx * STAGE_BYTES;
        #pragma unroll
        for (int ks = 0; ks < 4; ks++) {
            uint32_t ah[4][4], bh[4][2];
            const int cA = ((2 * ks + (g >> 1)) ^ r) << 4;
            #pragma unroll
            for (int mi = 0; mi < 4; mi++) {
                uint32_t rowA = warp_m * 64 + mi * 16 + ((g & 1) << 3) + r;
                ldsm4(ah[mi][0], ah[mi][1], ah[mi][2], ah[mi][3], st + rowA * 128 + cA);
            }
            const int cB = ((2 * ks + (g & 1)) ^ r) << 4;
            #pragma unroll
            for (int p = 0; p < 2; p++) {
                uint32_t rowB = warp_n * 32 + ((2 * p + (g >> 1)) << 3) + r;
                uint32_t t0, t1, t2, t3;
                ldsm4(t0, t1, t2, t3, st + OFF_B + rowB * 128 + cB);
                bh[2*p][0] = t0; bh[2*p][1] = t1; bh[2*p+1][0] = t2; bh[2*p+1][1] = t3;
            }
            #pragma unroll
            for (int mi = 0; mi < 4; mi++)
                #pragma unroll
                for (int ni = 0; ni < 4; ni++)
                    mma16816(acc[mi][ni], ah[mi], bh[ni]);
        }
        sidx++; if (sidx >= NSTAGE) sidx = 0;
    }

    #pragma unroll
    for (int mi = 0; mi < 4; mi++) {
        #pragma unroll
        for (int ni = 0; ni < 4; ni++) {
            const int row0 = blockIdx.y * BM + warp_m * 64 + mi * 16 + (lane >> 2);
            const int col  = blockIdx.x * BN + warp_n * 32 + ni * 8 + 2 * (lane & 3);
            float bx = 0.f, by = 0.f;
            if (bias) { bx = __ldg(bias + col); by = __ldg(bias + col + 1); }
            #pragma unroll
            for (int h = 0; h < 2; h++) {
                float x0 = acc[mi][ni][2*h + 0] * scale + bx;
                float x1 = acc[mi][ni][2*h + 1] * scale + by;
                const size_t o = (size_t)(z * sC) + (size_t)(row0 + 8*h) * ldc + col;
                if (Cf) *(float2*)&Cf[o] = make_float2(x0, x1);
                if (Ch) {
                    union { __half b[2]; uint32_t u; } H;
                    H.b[0] = __float2half(x0); H.b[1] = __float2half(x1);
                    *(uint32_t*)&Ch[o] = H.u;
                }
            }
        }
    }
}

// ---------------- fused q/k/v conversion + row stats ----------------
__global__ __launch_bounds__(256)
void conv_qkv_kernel(const float* __restrict__ q, const float* __restrict__ k,
                     const float* __restrict__ v,
                     __half* __restrict__ qh, __half* __restrict__ kh,
                     __half* __restrict__ vh)
{
    const int which = blockIdx.y;
    const float* src = (which == 0) ? q : (which == 1) ? k : v;
    __half* dst      = (which == 0) ? qh : (which == 1) ? kh : vh;

    int i = (blockIdx.x * blockDim.x + threadIdx.x) * 8;
    float4 v0 = *(const float4*)(src + i);
    float4 v1 = *(const float4*)(src + i + 4);
    float x[8] = {v0.x, v0.y, v0.z, v0.w, v1.x, v1.y, v1.z, v1.w};
    union { uint4 qd; __half b[8]; } H;
    #pragma unroll
    for (int j = 0; j < 8; j++) H.b[j] = __float2half(x[j]);
    *(uint4*)(dst + i) = H.qd;

    // row stats: first 8 elements of each row == this thread's chunk when i%1024==0
    if (which < 2 && (i & (DD - 1)) == 0) {
        float s = 0.f, t = 0.f;
        #pragma unroll
        for (int m = 0; m < NQ; m++) {
            float tv = tanhf(x[m]);
            float a = expf(tv);
            s += a; t += a * tv;
        }
        int row = i >> 10;
        if (which == 0) { g_Sa[row] = s; g_Ta[row] = t; }
        else            { g_Sb[row] = s; g_Tb[row] = t; }
    }
}

// ---------------- fused weight conversion (Wq,Wk,Wv,Wo) ----------------
__global__ __launch_bounds__(256)
void conv_w_kernel(const float* __restrict__ wq, const float* __restrict__ wk,
                   const float* __restrict__ wv, const float* __restrict__ wo)
{
    const int which = blockIdx.y;
    const float* src = (which == 0) ? wq : (which == 1) ? wk : (which == 2) ? wv : wo;
    __half* dst = (__half*)g_wh[which];
    int i = (blockIdx.x * blockDim.x + threadIdx.x) * 8;
    float4 v0 = *(const float4*)(src + i);
    float4 v1 = *(const float4*)(src + i + 4);
    float x[8] = {v0.x, v0.y, v0.z, v0.w, v1.x, v1.y, v1.z, v1.w};
    union { uint4 qd; __half b[8]; } H;
    #pragma unroll
    for (int j = 0; j < 8; j++) H.b[j] = __float2half(x[j]);
    *(uint4*)(dst + i) = H.qd;
}

// ---------------- fp16 transpose: VT[b][d][t] = V[b][t][d] ----------------
__global__ void transpose_h_kernel(const __half* __restrict__ V, __half* __restrict__ T)
{
    __shared__ __half tile[32][33];
    const int b = blockIdx.z;
    const __half* Vb = V + (size_t)b * SS * DD;
    __half* Tb = T + (size_t)b * DD * SS;
    const int x = blockIdx.x * 32 + threadIdx.x;
    const int y0 = blockIdx.y * 32;
    #pragma unroll
    for (int i = threadIdx.y; i < 32; i += 8)
        tile[i][threadIdx.x] = Vb[(size_t)(y0 + i) * DD + x];
    __syncthreads();
    const int t = y0 + threadIdx.x;
    #pragma unroll
    for (int i = threadIdx.y; i < 32; i += 8)
        Tb[(size_t)(blockIdx.x * 32 + i) * SS + t] = tile[threadIdx.x][i];
}

// ---------------- fused quantum + softmax (table-driven, MUFU-free) ----------------
__global__ __launch_bounds__(256)
void softmax_quantum_kernel(float* __restrict__ attn_out, __half* __restrict__ Ph)
{
    const int row = blockIdx.x;
    const int b   = row >> 10;
    const int tid = threadIdx.x;
    const float* sc = &g_SC[(size_t)row * SS];
    const float Sa = g_Sa[row], Ta = g_Ta[row];

    const float hz = (TBL_Z1 - TBL_Z0) / TBL_N;
    const float inv_hz = (float)TBL_N / (TBL_Z1 - TBL_Z0);
    const float he = (0.0f - TBL_E0) / TBL_N;
    const float inv_he = (float)TBL_N / (0.0f - TBL_E0);

    __shared__ float sred[8];
    float v[4];
    float mx = -1e30f;

    const int j0 = tid * 4;
    float4 scv = *(const float4*)(sc + j0);
    float4 Sbv = *(const float4*)(&g_Sb[b * SS + j0]);
    float4 Tbv = *(const float4*)(&g_Tb[b * SS + j0]);
    const float scA[4] = {scv.x, scv.y, scv.z, scv.w};
    const float SbA[4] = {Sbv.x, Sbv.y, Sbv.z, Sbv.w};
    const float TbA[4] = {Tbv.x, Tbv.y, Tbv.z, Tbv.w};

    #pragma unroll
    for (int u = 0; u < 4; u++) {
        float Z = Sa + SbA[u];
        float tz = (Z - TBL_Z0) * inv_hz;
        int k = (int)tz;                        // Z in (5.88,43.5) -> in range
        float4 c4 = __ldg(&g_tblZ[k]);
        float fz = fmaf(-hz, (float)k, Z - TBL_Z0);
        float lnZ = fmaf(c4.y, fz, c4.x);
        float rz  = fmaf(c4.w, fz, c4.z);
        float c = scA[u] + 0.3f * (lnZ - (Ta + TbA[u]) * rz);
        v[u] = c;
        mx = fmaxf(mx, c);
    }
    #pragma unroll
    for (int o = 16; o > 0; o >>= 1) mx = fmaxf(mx, __shfl_xor_sync(0xffffffffu, mx, o));
    if ((tid & 31) == 0) sred[tid >> 5] = mx;
    __syncthreads();
    if (tid == 0) {
        float x = sred[0];
        #pragma unroll
        for (int w = 1; w < 8; w++) x = fmaxf(x, sred[w]);
        sred[0] = x;
    }
    __syncthreads();
    mx = sred[0];
    __syncthreads();

    float sum = 0.f;
    #pragma unroll
    for (int u = 0; u < 4; u++) {
        float x = v[u] - mx;                   // <= 0
        float te = (x - TBL_E0) * inv_he;
        te = fmaxf(te, 0.0f);                  // clamp x < E0 -> ~0
        int k = (int)te;
        k = (k > TBL_N - 1) ? (TBL_N - 1) : k;
        float2 e2 = __ldg(&g_tblE[k]);
        float fe = fmaf(-he, (float)k, x - TBL_E0);
        float p = fmaf(e2.y, fe, e2.x);
        v[u] = p;
        sum += p;
    }
    #pragma unroll
    for (int o = 16; o > 0; o >>= 1) sum += __shfl_xor_sync(0xffffffffu, sum, o);
    if ((tid & 31) == 0) sred[tid >> 5] = sum;
    __syncthreads();
    if (tid == 0) {
        float x = 0.f;
        #pragma unroll
        for (int w = 0; w < 8; w++) x += sred[w];
        sred[0] = x;
    }
    __syncthreads();
    const float inv = 1.0f / sred[0];

    float4 po;
    union { uint2 u2; __half b[4]; } Hp;
    po.x = v[0] * inv; po.y = v[1] * inv; po.z = v[2] * inv; po.w = v[3] * inv;
    #pragma unroll
    for (int u = 0; u < 4; u++) Hp.b[u] = __float2half(((float*)&po)[u]);
    if (attn_out) *(float4*)&attn_out[(size_t)row * SS + j0] = po;
    *(uint2*)&Ph[(size_t)row * SS + j0] = Hp.u2;
}

// ---------------- launcher ----------------
#define SYMF(ptr, sym) cudaGetSymbolAddress((void**)&ptr, sym)

extern "C" void kernel_launch(void* const* d_in, const int* in_sizes, int n_in,
                              void* d_out, int out_size)
{
    const float* query = (const float*)d_in[0];
    const float* key   = (const float*)d_in[1];
    const float* value = (const float*)d_in[2];
    const float* Wq    = (const float*)d_in[3];
    const float* bq    = (const float*)d_in[4];
    const float* Wk    = (const float*)d_in[5];
    const float* bk    = (const float*)d_in[6];
    const float* Wv    = (const float*)d_in[7];
    const float* bv    = (const float*)d_in[8];
    const float* Wo    = (const float*)d_in[9];
    const float* bo    = (const float*)d_in[10];
    float* out = (float*)d_out;

    __half *qh,*kh,*vh,*Qh,*Kh,*Vh,*VTh,*Ph,*ATh;
    __half *whBase;
    float *SCp;
    SYMF(qh,g_qh); SYMF(kh,g_kh); SYMF(vh,g_vh);
    SYMF(whBase,g_wh);
    SYMF(Qh,g_Qh); SYMF(Kh,g_Kh); SYMF(Vh,g_Vh); SYMF(VTh,g_VTh);
    SYMF(Ph,g_Ph); SYMF(ATh,g_ATh);
    SYMF(SCp,g_SC);
    __half* wqh = whBase;
    __half* wkh = whBase + (size_t)NW;
    __half* wvh = whBase + (size_t)2*NW;
    __half* woh = whBase + (size_t)3*NW;

    const long OUT_N = (long)NM;
    float* attn_out = ((long)out_size >= 2 * OUT_N) ? (out + OUT_N) : nullptr;

    cudaFuncSetAttribute(tc_gemm_nt, cudaFuncAttributeMaxDynamicSharedMemorySize, SMEM_GEMM);

    dim3 gProj(DD/BN, BSROWS/BM, 1);   // (8, 32)
    dim3 gBat (SS/BN, SS/BM, BB);      // (8, 8, 4)

    // 1: tables   2: q/k/v conv + row stats   3: weight convs
    build_tables_kernel<<<TBL_N/256, 256>>>();
    conv_qkv_kernel<<<dim3(NM/2048, 3), 256>>>(query, key, value, qh, kh, vh);
    conv_w_kernel<<<dim3(NW/2048, 4), 256>>>(Wq, Wk, Wv, Wo);

    // 4,5,6: projections (launch 6 = V GEMM, profiled by ncu)
    tc_gemm_nt<<<gProj, NT_THREADS, SMEM_GEMM>>>(qh, wqh, nullptr, Qh, bq, 1.f, DD, DD, 0, 0, 0);
    tc_gemm_nt<<<gProj, NT_THREADS, SMEM_GEMM>>>(kh, wkh, nullptr, Kh, bk, 1.f, DD, DD, 0, 0, 0);
    tc_gemm_nt<<<gProj, NT_THREADS, SMEM_GEMM>>>(vh, wvh, nullptr, Vh, bv, 1.f, DD, DD, 0, 0, 0);

    transpose_h_kernel<<<dim3(32,32,BB), dim3(32,8)>>>(Vh, VTh);

    // classical scores (scaled)
    tc_gemm_nt<<<gBat, NT_THREADS, SMEM_GEMM>>>(Qh, Kh, SCp, nullptr, nullptr, CLS_SCALE,
                                                DD, SS, (long)SS*DD, (long)SS*DD, (long)SS*SS);

    // quantum + softmax (tables)
    softmax_quantum_kernel<<<BSROWS, 256>>>(attn_out, Ph);

    // attended = attn @ V (NT via VT)
    tc_gemm_nt<<<gBat, NT_THREADS, SMEM_GEMM>>>(Ph, VTh, nullptr, ATh, nullptr, 1.f,
                                                SS, DD, (long)SS*SS, (long)DD*SS, (long)SS*DD);

    // output projection
    tc_gemm_nt<<<gProj, NT_THREADS, SMEM_GEMM>>>(ATh, woh, out, nullptr, bo, 1.f, DD, DD, 0, 0, 0);
}